// round 17
// baseline (speedup 1.0000x reference)
#include <cuda_runtime.h>
#include <cuda_bf16.h>

#define T_STEPS 4096
#define M_BATCH 512
#define D_IN    11
#define NH      51
#define A1S     64      // x[11] | h1[51] | pad2  -> 16 ul2 per row
#define A2S     104     // h1[51] | h2[51] | pad2 -> 52 u64 per row
#define THREADS 256
#define BLOCKS  128     // 128 * 4 rows = 512

typedef unsigned long long u64;

__device__ __forceinline__ float tanha(float x) {
    float y; asm("tanh.approx.f32 %0, %1;" : "=f"(y) : "f"(x)); return y;
}
__device__ __forceinline__ float siga(float x) {
    return fmaf(0.5f, tanha(0.5f * x), 0.5f);
}
__device__ __forceinline__ u64 fma2(u64 a, u64 b, u64 c) {
    u64 d;
    asm("fma.rn.f32x2 %0, %1, %2, %3;" : "=l"(d) : "l"(a), "l"(b), "l"(c));
    return d;
}
__device__ __forceinline__ u64 pack2(float lo, float hi) {
    u64 r;
    asm("mov.b64 %0, {%1, %2};" : "=l"(r) : "f"(lo), "f"(hi));
    return r;
}
__device__ __forceinline__ float sum2(u64 v) {
    float lo, hi;
    asm("mov.b64 {%0, %1}, %2;" : "=f"(lo), "=f"(hi) : "l"(v));
    return lo + hi;
}

__global__ void __launch_bounds__(THREADS, 1)
lstm2_persistent_kernel(const float* __restrict__ x,
                        const float* __restrict__ Wih1, const float* __restrict__ Whh1,
                        const float* __restrict__ bih1, const float* __restrict__ bhh1,
                        const float* __restrict__ Wih2, const float* __restrict__ Whh2,
                        const float* __restrict__ bih2, const float* __restrict__ bhh2,
                        const float* __restrict__ Wlin, const float* __restrict__ blin,
                        float* __restrict__ out)
{
    __shared__ float A1[2][4][A1S];      // [buf][row][ x | h1 | pad ]
    __shared__ float A2[2][4][A2S];      // [buf][row][ h1 | h2 | pad ]
    __shared__ float PO[2][4][64];       // [buf][row][cell] output partials (pads zero)

    const int tid   = threadIdx.x;
    const int wid   = tid >> 5;
    const int lane  = tid & 31;
    const int mbase = blockIdx.x * 4;
    const bool is_gate = (tid < 204);            // 51 cells x 4 K-quarters
    const int q = tid & 3;                       // K-quarter AND owned batch row
    const int n = tid >> 2;                      // cell index 0..50
    const unsigned smask = (wid == 6) ? 0x00000fffu : 0xffffffffu;

    // ---- register weights: 4 gates (i,f,g,o) of cell n, K-quarter q ----
    u64 w1[4][8];    // L1: 16 floats per quarter (padded K=64)
    u64 w2[4][13];   // L2: 26 floats per quarter (padded K=104)
    float b1[4] = {0,0,0,0}, b2[4] = {0,0,0,0};
    #pragma unroll
    for (int G = 0; G < 4; ++G) {
        #pragma unroll
        for (int i = 0; i < 8; ++i)  w1[G][i] = 0ull;
        #pragma unroll
        for (int i = 0; i < 13; ++i) w2[G][i] = 0ull;
    }
    if (is_gate) {
        #pragma unroll
        for (int G = 0; G < 4; ++G) {
            const int col = G * NH + n;
            #pragma unroll
            for (int i = 0; i < 8; ++i) {
                int k = 16 * q + 2 * i;
                float lo = 0.f, hi = 0.f;
                if (k < D_IN)            lo = Wih1[col * D_IN + k];
                else if (k < D_IN + NH)  lo = Whh1[col * NH + (k - D_IN)];
                int k1 = k + 1;
                if (k1 < D_IN)           hi = Wih1[col * D_IN + k1];
                else if (k1 < D_IN + NH) hi = Whh1[col * NH + (k1 - D_IN)];
                w1[G][i] = pack2(lo, hi);
            }
            #pragma unroll
            for (int i = 0; i < 13; ++i) {
                int k = 26 * q + 2 * i;
                float lo = 0.f, hi = 0.f;
                if (k < NH)              lo = Wih2[col * NH + k];
                else if (k < 2 * NH)     lo = Whh2[col * NH + (k - NH)];
                int k1 = k + 1;
                if (k1 < NH)             hi = Wih2[col * NH + k1];
                else if (k1 < 2 * NH)    hi = Whh2[col * NH + (k1 - NH)];
                w2[G][i] = pack2(lo, hi);
            }
            b1[G] = bih1[col] + bhh1[col];
            b2[G] = bih2[col] + bhh2[col];
        }
    }
    const float wl = is_gate ? Wlin[n] : 0.f;
    const float bl = blin[0];
    float c1 = 0.f, c2 = 0.f;                    // cell states for (row q, cell n)

    // ---- init shared ----
    for (int i = tid; i < 2 * 4 * A1S; i += THREADS) (&A1[0][0][0])[i] = 0.f;
    for (int i = tid; i < 2 * 4 * A2S; i += THREADS) (&A2[0][0][0])[i] = 0.f;
    for (int i = tid; i < 2 * 4 * 64;  i += THREADS) (&PO[0][0][0])[i] = 0.f;
    if (tid < 44) {                              // x(0) -> buffer 0
        int r = tid / D_IN, k = tid - r * D_IN;
        A1[0][r][k] = x[(mbase + r) * D_IN + k];
    }
    __syncthreads();

    // ONE phase / ONE barrier per step.
    // Phase i: gemm+epi L1(i) [needs x(i),h1(i-1) in buf i&1]
    //          gemm+epi L2(i-1) [needs h1(i-1),h2(i-2) in buf i&1]
    //          helpers: x(i+1) -> buf (i+1)&1 ; reduce PO[i&1] (= step i-2)
    for (int i = 0; i <= T_STEPS + 1; ++i) {
        const int bA = i & 1, bB = (i + 1) & 1;

        if (is_gate) {
            // ===== Layer-1 gemm (step i) + its epilogue =====
            if (i < T_STEPS) {
                u64 acc[4][4];
                #pragma unroll
                for (int G = 0; G < 4; ++G)
                    #pragma unroll
                    for (int r = 0; r < 4; ++r) acc[G][r] = 0ull;
                const ulonglong2* base = (const ulonglong2*)&A1[bA][0][0];  // 16 ul2/row
                #pragma unroll
                for (int ii = 0; ii < 4; ++ii) {
                    #pragma unroll
                    for (int r = 0; r < 4; ++r) {
                        ulonglong2 u = base[r * 16 + 4 * q + ii];
                        #pragma unroll
                        for (int G = 0; G < 4; ++G) {
                            acc[G][r] = fma2(w1[G][2 * ii],     u.x, acc[G][r]);
                            acc[G][r] = fma2(w1[G][2 * ii + 1], u.y, acc[G][r]);
                        }
                    }
                }
                float s[4][4];
                #pragma unroll
                for (int G = 0; G < 4; ++G)
                    #pragma unroll
                    for (int r = 0; r < 4; ++r) s[G][r] = sum2(acc[G][r]);
                #pragma unroll
                for (int G = 0; G < 4; ++G)
                    #pragma unroll
                    for (int r = 0; r < 4; ++r) {
                        s[G][r] += __shfl_xor_sync(smask, s[G][r], 1, 4);
                        s[G][r] += __shfl_xor_sync(smask, s[G][r], 2, 4);
                    }
                // epilogue for (row q, cell n)
                float gi = s[0][q] + b1[0], gf = s[1][q] + b1[1];
                float gg = s[2][q] + b1[2], go = s[3][q] + b1[3];
                c1 = siga(gf) * c1 + siga(gi) * tanha(gg);
                float h = siga(go) * tanha(c1);
                A1[bB][q][D_IN + n] = h;        // h1(i) for L1(i+1)
                A2[bB][q][n]        = h;        // h1(i) for L2(i) next phase
            }
            // ===== Layer-2 gemm (step i-1) + its epilogue =====
            if (i >= 1 && i <= T_STEPS) {
                u64 acc[4][4];
                #pragma unroll
                for (int G = 0; G < 4; ++G)
                    #pragma unroll
                    for (int r = 0; r < 4; ++r) acc[G][r] = 0ull;
                const u64* base = (const u64*)&A2[bA][0][0];                // 52 u64/row
                #pragma unroll
                for (int ii = 0; ii < 13; ++ii) {
                    #pragma unroll
                    for (int r = 0; r < 4; ++r) {
                        u64 a = base[r * 52 + 13 * q + ii];
                        #pragma unroll
                        for (int G = 0; G < 4; ++G)
                            acc[G][r] = fma2(w2[G][ii], a, acc[G][r]);
                    }
                }
                float s[4][4];
                #pragma unroll
                for (int G = 0; G < 4; ++G)
                    #pragma unroll
                    for (int r = 0; r < 4; ++r) s[G][r] = sum2(acc[G][r]);
                #pragma unroll
                for (int G = 0; G < 4; ++G)
                    #pragma unroll
                    for (int r = 0; r < 4; ++r) {
                        s[G][r] += __shfl_xor_sync(smask, s[G][r], 1, 4);
                        s[G][r] += __shfl_xor_sync(smask, s[G][r], 2, 4);
                    }
                float gi = s[0][q] + b2[0], gf = s[1][q] + b2[1];
                float gg = s[2][q] + b2[2], go = s[3][q] + b2[3];
                c2 = siga(gf) * c2 + siga(gi) * tanha(gg);
                float h = siga(go) * tanha(c2);
                A2[bB][q][NH + n] = h;          // h2(i-1) for L2(i) next phase
                PO[bB][q][n] = h * wl;          // output partial, step i-1
            }
        } else if (wid == 6) {
            // helper lanes 12..31 of warp 6: prefetch x(i+1) into buf bB
            if (i + 1 < T_STEPS) {
                int j0 = lane - 12;
                #pragma unroll
                for (int tt = 0; tt < 3; ++tt) {
                    int j = j0 + 20 * tt;
                    if (j < 44) {
                        int r = j / D_IN, k = j - r * D_IN;
                        A1[bB][r][k] = x[((i + 1) * M_BATCH + mbase + r) * D_IN + k];
                    }
                }
            }
        } else {
            // warp 7: reduce PO[bA] (= step i-2) and store outputs
            if (i >= 2) {
                #pragma unroll
                for (int r = 0; r < 4; ++r) {
                    float v = PO[bA][r][lane] + PO[bA][r][32 + lane];  // pads zero
                    #pragma unroll
                    for (int off = 16; off > 0; off >>= 1)
                        v += __shfl_down_sync(0xffffffffu, v, off);
                    if (lane == 0)
                        out[(mbase + r) * T_STEPS + (i - 2)] = v + bl;
                }
            }
        }
        __syncthreads();
    }
}

extern "C" void kernel_launch(void* const* d_in, const int* in_sizes, int n_in,
                              void* d_out, int out_size) {
    const float* x    = (const float*)d_in[0];
    const float* Wih1 = (const float*)d_in[1];
    const float* Whh1 = (const float*)d_in[2];
    const float* bih1 = (const float*)d_in[3];
    const float* bhh1 = (const float*)d_in[4];
    const float* Wih2 = (const float*)d_in[5];
    const float* Whh2 = (const float*)d_in[6];
    const float* bih2 = (const float*)d_in[7];
    const float* bhh2 = (const float*)d_in[8];
    const float* Wlin = (const float*)d_in[9];
    const float* blin = (const float*)d_in[10];
    float* out = (float*)d_out;

    lstm2_persistent_kernel<<<BLOCKS, THREADS>>>(
        x, Wih1, Whh1, bih1, bhh1, Wih2, Whh2, bih2, bhh2, Wlin, blin, out);
}